// round 10
// baseline (speedup 1.0000x reference)
#include <cuda_runtime.h>
#include <math.h>

#define DIM_EI  4096
#define DIM_CA3 8192
#define DIM_CA1 8192
#define DIM_EO  4096

static constexpr float BETA  = 10.0f;
static constexpr float ALPHA = 0.01f;

// ---------------- device scratch ----------------
__device__ float g_h1[DIM_CA3];
__device__ float g_h3[DIM_CA1];
__device__ float g_h2[DIM_CA1];
__device__ float g_h4[DIM_EO];
__device__ float g_xca3[DIM_CA3];
__device__ float g_IS[DIM_CA1];
__device__ float g_xca1[DIM_CA1];
__device__ float g_th2;                // threshold for h2 (x_ca1 apply)
__device__ int   g_nnz_idx[DIM_CA3];   // x_ca3 nonzeros (ordered)
__device__ float g_nnz_val[DIM_CA3];
__device__ int   g_nnz_cnt;
__device__ int   g_is_idx[DIM_CA1];    // IS nonzero indices (unordered ok)
__device__ unsigned g_ctr_out;         // zero-init; self-resets each replay

// ---------------- helpers ----------------
__device__ __forceinline__ unsigned f2u(float f) {
    unsigned u = __float_as_uint(f);
    return (u & 0x80000000u) ? ~u : (u | 0x80000000u);
}
__device__ __forceinline__ float u2f(unsigned u) {
    return __uint_as_float((u & 0x80000000u) ? (u & 0x7fffffffu) : ~u);
}
__device__ __forceinline__ float sigm(float z) { return 1.0f / (1.0f + expf(-z)); }

// Conflict-free smem histogram add: aggregate equal bins within the warp.
__device__ __forceinline__ void hist_add(unsigned* s_hist, int bin, bool pred) {
    unsigned active = __ballot_sync(0xffffffffu, pred);
    if (pred) {
        unsigned mask = __match_any_sync(active, bin);
        int leader = __ffs(mask) - 1;
        if ((int)(threadIdx.x & 31) == leader)
            atomicAdd(&s_hist[bin], (unsigned)__popc(mask));
    }
}

// Warp 0 finds the bin containing the k-th largest from a 256-bin histogram.
__device__ __forceinline__ void find_bin_warp0(const unsigned* s_hist, int k,
                                               int* s_bin, int* s_k) {
    if (threadIdx.x < 32) {
        int lane = threadIdx.x;
        unsigned b[8]; unsigned tot = 0;
        #pragma unroll
        for (int j = 0; j < 8; j++) { b[j] = s_hist[lane * 8 + j]; tot += b[j]; }
        unsigned suf = tot;
        #pragma unroll
        for (int o = 1; o < 32; o <<= 1) {
            unsigned n = __shfl_down_sync(0xffffffffu, suf, o);
            if (lane + o < 32) suf += n;
        }
        unsigned above = suf - tot;
        unsigned ge[8]; unsigned run = above;
        #pragma unroll
        for (int j = 7; j >= 0; j--) { run += b[j]; ge[j] = run; }
        unsigned gt = above;
        #pragma unroll
        for (int j = 7; j >= 0; j--) {
            if (ge[j] >= (unsigned)k && gt < (unsigned)k) {
                *s_bin = lane * 8 + j;
                *s_k   = k - (int)gt;
            }
            gt = ge[j];
        }
    }
}

// Exact K-th largest, register values. blockDim >= 256.
template<int M>
__device__ float kth_fast_reg(const unsigned* uv, int K) {
    __shared__ unsigned s_hist[256];
    __shared__ int s_bin, s_k;
    unsigned prefix = 0;
    int k = K;
    #pragma unroll
    for (int shift = 24; shift >= 0; shift -= 8) {
        if (threadIdx.x < 256) s_hist[threadIdx.x] = 0;
        __syncthreads();
        unsigned hi = (shift == 24) ? 0u : (0xFFFFFFFFu << (shift + 8));
        #pragma unroll
        for (int j = 0; j < M; j++) {
            unsigned u = uv[j];
            hist_add(s_hist, (u >> shift) & 255, (u & hi) == prefix);
        }
        __syncthreads();
        find_bin_warp0(s_hist, k, &s_bin, &s_k);
        __syncthreads();
        prefix |= ((unsigned)s_bin) << shift;
        k = s_k;
    }
    return u2f(prefix);
}

// Exact K-th largest of x[0..n), global-read variant.
__device__ float kth_fast_global(const float* __restrict__ x, int n, int K) {
    __shared__ unsigned s_hist[256];
    __shared__ int s_bin, s_k;
    unsigned prefix = 0;
    int k = K;
    #pragma unroll
    for (int shift = 24; shift >= 0; shift -= 8) {
        if (threadIdx.x < 256) s_hist[threadIdx.x] = 0;
        __syncthreads();
        unsigned hi = (shift == 24) ? 0u : (0xFFFFFFFFu << (shift + 8));
        for (int i = threadIdx.x; i < n; i += blockDim.x) {
            unsigned u = f2u(x[i]);
            hist_add(s_hist, (u >> shift) & 255, (u & hi) == prefix);
        }
        __syncthreads();
        find_bin_warp0(s_hist, k, &s_bin, &s_k);
        __syncthreads();
        prefix |= ((unsigned)s_bin) << shift;
        k = s_k;
    }
    return u2f(prefix);
}

// ---------------- K1: h1 = W_ei_ca3 @ x, h3 = W_ei_ca1 @ x (one warp/row) -------------
__global__ __launch_bounds__(256) void matvec_dual_kernel(
        const float* __restrict__ Wa, const float* __restrict__ Wb,
        const float* __restrict__ x) {
    int warp = threadIdx.x >> 5, lane = threadIdx.x & 31;
    int row = blockIdx.x * 8 + warp;
    const float* W; float* out; int r;
    if (row < DIM_CA3) { W = Wa; out = g_h1; r = row; }
    else               { W = Wb; out = g_h3; r = row - DIM_CA3; }
    const float4* w4 = reinterpret_cast<const float4*>(W) + (size_t)r * (DIM_EI / 4);
    const float4* x4 = reinterpret_cast<const float4*>(x);
    float acc = 0.0f;
    #pragma unroll 8
    for (int i = lane; i < DIM_EI / 4; i += 32) {
        float4 w = __ldcs(&w4[i]);
        float4 v = __ldg(&x4[i]);
        acc += w.x * v.x + w.y * v.y + w.z * v.z + w.w * v.w;
    }
    #pragma unroll
    for (int o = 16; o; o >>= 1) acc += __shfl_down_sync(0xffffffffu, acc, o);
    if (lane == 0) out[r] = acc;
}

// ---------------- K2: block0 -> top-2(h1) tournament, zeros, 2 sigmoids;
//                      block1 -> top-100(h3) radix, zeros, ~100 sigmoids --------------
__global__ void stageA_kernel() {
    int lane = threadIdx.x & 31, wid = threadIdx.x >> 5;
    int base = threadIdx.x * 8;
    if (blockIdx.x == 0) {
        // ---- tournament (max, 2nd max) -> threshold ----
        float xv[8];
        float m1 = -1e38f, m2 = -1e38f;
        #pragma unroll
        for (int j = 0; j < 8; j++) {
            float v = g_h1[base + j]; xv[j] = v;
            if (v > m1)      { m2 = m1; m1 = v; }
            else if (v > m2) { m2 = v; }
        }
        #pragma unroll
        for (int o = 16; o; o >>= 1) {
            float o1 = __shfl_down_sync(0xffffffffu, m1, o);
            float o2 = __shfl_down_sync(0xffffffffu, m2, o);
            float big = fmaxf(m1, o1);
            float sec = fmaxf(fminf(m1, o1), fmaxf(m2, o2));
            m1 = big; m2 = sec;
        }
        __shared__ float sm1[32], sm2[32];
        __shared__ float s_th;
        if (lane == 0) { sm1[wid] = m1; sm2[wid] = m2; }
        __syncthreads();
        if (threadIdx.x < 32) {
            float a1 = sm1[lane], a2 = sm2[lane];
            #pragma unroll
            for (int o = 16; o; o >>= 1) {
                float o1 = __shfl_down_sync(0xffffffffu, a1, o);
                float o2 = __shfl_down_sync(0xffffffffu, a2, o);
                float big = fmaxf(a1, o1);
                float sec = fmaxf(fminf(a1, o1), fmaxf(a2, o2));
                a1 = big; a2 = sec;
            }
            if (lane == 0) s_th = a2;
        }
        __syncthreads();
        float th = s_th;
        // ---- zeros + ordered compaction (NO sigmoid here) ----
        int keep[8]; int cnt = 0;
        #pragma unroll
        for (int j = 0; j < 8; j++) {
            int kp = (xv[j] >= th);
            g_xca3[base + j] = 0.0f;       // overwritten below for keeps
            keep[j] = kp; cnt += kp;
        }
        __shared__ int wsum[32];
        int incl = cnt;
        #pragma unroll
        for (int o = 1; o < 32; o <<= 1) {
            int n = __shfl_up_sync(0xffffffffu, incl, o);
            if (lane >= o) incl += n;
        }
        if (lane == 31) wsum[wid] = incl;
        __syncthreads();
        if (threadIdx.x == 0) {
            int s = 0;
            #pragma unroll
            for (int i = 0; i < 32; i++) { int c = wsum[i]; wsum[i] = s; s += c; }
            g_nnz_cnt = s;
        }
        __syncthreads();
        int off = wsum[wid] + incl - cnt;
        #pragma unroll
        for (int j = 0; j < 8; j++)
            if (keep[j]) { g_nnz_idx[off] = base + j; ++off; }
        __syncthreads();
        // ---- phase 2: sigmoids only for the ~2 kept elements ----
        int total = g_nnz_cnt;
        for (int i = threadIdx.x; i < total; i += blockDim.x) {
            int idx = g_nnz_idx[i];
            float v = sigm(BETA * (g_h1[idx] - th));
            g_nnz_val[i] = v;
            g_xca3[idx] = v;
        }
    } else {
        // ---- radix threshold for top-100(h3) ----
        float xv[8]; unsigned uv[8];
        #pragma unroll
        for (int j = 0; j < 8; j++) { xv[j] = g_h3[base + j]; uv[j] = f2u(xv[j]); }
        float th = kth_fast_reg<8>(uv, 100);
        // zeros + unordered compaction (writes are pure functions of idx)
        __shared__ int s_cnt;
        if (threadIdx.x == 0) s_cnt = 0;
        __syncthreads();
        int loc[8]; int cnt = 0;
        #pragma unroll
        for (int j = 0; j < 8; j++) {
            g_IS[base + j] = 0.0f;
            if (xv[j] >= th) loc[cnt++] = base + j;
        }
        if (cnt) {
            int pos = atomicAdd(&s_cnt, cnt);
            for (int j = 0; j < cnt; j++) g_is_idx[pos + j] = loc[j];
        }
        __syncthreads();
        int total = s_cnt;
        // phase 2: ~100 sigmoids spread over the block (loop-bound branch, no
        // predicated MUFU for non-participants)
        for (int i = threadIdx.x; i < total; i += blockDim.x) {
            int idx = g_is_idx[i];
            g_IS[idx] = sigm(BETA * (g_h3[idx] - th));
        }
    }
}

// ---------------- gather h2 across 32 blocks ----------------
__global__ void gather_h2_kernel(const float* __restrict__ W3) {
    int i = blockIdx.x * blockDim.x + threadIdx.x;   // one row per thread
    int cnt = g_nnz_cnt;
    size_t rowoff = (size_t)i * DIM_CA3;
    float acc = 0.0f;
    for (int k = 0; k < cnt; k++)
        acc += __ldg(&W3[rowoff + g_nnz_idx[k]]) * g_nnz_val[k];
    g_h2[i] = acc;
}

// ---------------- stageC threshold only (1 block) ----------------
__global__ void stageC_th_kernel() {
    float th = kth_fast_global(g_h2, DIM_CA1, 100);
    if (threadIdx.x == 0) g_th2 = th;
}

// ---------------- dense x_ca1 apply: 32 blocks (MUFU spread across SMs) ---------------
__global__ void apply_xca1_kernel() {
    int i = blockIdx.x * blockDim.x + threadIdx.x;
    float th = g_th2;
    g_xca1[i] = sigm(BETA * (g_h2[i] - th));   // flag=False: dense, no mask
}

// ---------------- update_W: (1-IS*a)*W + a*IS*x_ca3^T ----------------
__global__ void update_W_kernel(const float* __restrict__ W, float* __restrict__ out) {
    size_t idx = ((size_t)blockIdx.x * blockDim.x + threadIdx.x) * 4;
    int row = (int)(idx >> 13);
    int col = (int)(idx & (DIM_CA3 - 1));
    float s = g_IS[row];
    float a = 1.0f - s * ALPHA;
    float b = ALPHA * s;
    float4 w  = __ldcs(reinterpret_cast<const float4*>(W + idx));
    float4 xc = *reinterpret_cast<const float4*>(g_xca3 + col);
    float4 o;
    o.x = a * w.x + b * xc.x;
    o.y = a * w.y + b * xc.y;
    o.z = a * w.z + b * xc.z;
    o.w = a * w.w + b * xc.w;
    __stcs(reinterpret_cast<float4*>(out + idx), o);
}

// ---------------- matvec_out + fused top-50 tail (zeros + 50 sigmoids) ----------------
__global__ __launch_bounds__(256) void matvec_out_kernel(
        const float* __restrict__ W, float* __restrict__ out) {
    int warp = threadIdx.x >> 5, lane = threadIdx.x & 31;
    int tid = threadIdx.x;
    int row = blockIdx.x * 8 + warp;
    const float4* w4 = reinterpret_cast<const float4*>(W) + (size_t)row * (DIM_CA1 / 4);
    const float4* x4 = reinterpret_cast<const float4*>(g_xca1);
    float acc = 0.0f;
    #pragma unroll 8
    for (int i = lane; i < DIM_CA1 / 4; i += 32) {
        float4 w = __ldcs(&w4[i]);
        float4 v = __ldg(&x4[i]);
        acc += w.x * v.x + w.y * v.y + w.z * v.z + w.w * v.w;
    }
    #pragma unroll
    for (int o = 16; o; o >>= 1) acc += __shfl_down_sync(0xffffffffu, acc, o);
    if (lane == 0) {
        g_h4[row] = acc;
        __threadfence();
    }
    __syncthreads();
    __shared__ bool s_last;
    if (tid == 0) {
        unsigned t = atomicAdd(&g_ctr_out, 1u);
        s_last = (t == gridDim.x - 1);
    }
    __syncthreads();
    if (!s_last) return;
    __threadfence();
    float th = kth_fast_global(g_h4, DIM_EO, 50);
    // zeros + compaction, then ~50 sigmoids
    __shared__ int s_cnt;
    __shared__ int s_idx[256];     // expected ~50 kept; capped defensively
    if (tid == 0) s_cnt = 0;
    __syncthreads();
    for (int i = tid; i < DIM_EO; i += 256) {
        out[i] = 0.0f;
        if (g_h4[i] >= th) {
            int pos = atomicAdd(&s_cnt, 1);
            if (pos < 256) s_idx[pos] = i;
        }
    }
    __syncthreads();
    int total = s_cnt < 256 ? s_cnt : 256;
    for (int i = tid; i < total; i += 256) {
        int idx = s_idx[i];
        out[idx] = sigm(BETA * (g_h4[idx] - th));
    }
    // fallback (pathological tie flood): handle overflow densely
    if (s_cnt > 256) {
        for (int i = tid; i < DIM_EO; i += 256) {
            float xx = g_h4[i];
            if (xx >= th) out[i] = sigm(BETA * (xx - th));
        }
    }
    if (tid == 0) g_ctr_out = 0;
}

// ---------------- launch: R4 fork-join structure ----------------
extern "C" void kernel_launch(void* const* d_in, const int* in_sizes, int n_in,
                              void* d_out, int out_size) {
    const float* x_ei      = (const float*)d_in[0];
    const float* W_ei_ca3  = (const float*)d_in[1];
    const float* W_ei_ca1  = (const float*)d_in[2];
    const float* W_ca3_ca1 = (const float*)d_in[3];
    const float* W_ca1_eo  = (const float*)d_in[4];
    float* out = (float*)d_out;

    cudaStream_t s1;
    cudaStreamCreateWithFlags(&s1, cudaStreamNonBlocking);
    cudaEvent_t e_fork, e_join;
    cudaEventCreateWithFlags(&e_fork, cudaEventDisableTiming);
    cudaEventCreateWithFlags(&e_join, cudaEventDisableTiming);

    matvec_dual_kernel<<<(DIM_CA3 + DIM_CA1) / 8, 256>>>(W_ei_ca3, W_ei_ca1, x_ei);
    stageA_kernel<<<2, 1024>>>();

    // fork: B-chain on s1, concurrent with update_W on stream0
    cudaEventRecord(e_fork, 0);
    cudaStreamWaitEvent(s1, e_fork, 0);

    gather_h2_kernel<<<32, 256, 0, s1>>>(W_ca3_ca1);
    stageC_th_kernel<<<1, 1024, 0, s1>>>();
    apply_xca1_kernel<<<32, 256, 0, s1>>>();
    matvec_out_kernel<<<DIM_EO / 8, 256, 0, s1>>>(W_ca1_eo, out);

    update_W_kernel<<<(unsigned)((size_t)DIM_CA1 * DIM_CA3 / 4 / 256), 256>>>(W_ca3_ca1, out + DIM_EO);

    // join
    cudaEventRecord(e_join, s1);
    cudaStreamWaitEvent(0, e_join, 0);

    cudaEventDestroy(e_fork);
    cudaEventDestroy(e_join);
    cudaStreamDestroy(s1);
}

// round 11
// speedup vs baseline: 1.0044x; 1.0044x over previous
#include <cuda_runtime.h>
#include <math.h>

#define DIM_EI  4096
#define DIM_CA3 8192
#define DIM_CA1 8192
#define DIM_EO  4096

static constexpr float BETA  = 10.0f;
static constexpr float ALPHA = 0.01f;

// ---------------- device scratch ----------------
__device__ float g_h1[DIM_CA3];
__device__ float g_h3[DIM_CA1];
__device__ float g_h4[DIM_EO];
__device__ float g_xca3[DIM_CA3];
__device__ float g_IS[DIM_CA1];
__device__ float g_xca1[DIM_CA1];
__device__ int   g_nnz_idx[DIM_CA3];
__device__ float g_nnz_val[DIM_CA3];
__device__ int   g_nnz_cnt;
__device__ unsigned g_ctr;
__device__ float g_sink;          // DCE-blocker for the prefetch kernel

// ---------------- helpers ----------------
__device__ __forceinline__ unsigned f2u(float f) {
    unsigned u = __float_as_uint(f);
    return (u & 0x80000000u) ? ~u : (u | 0x80000000u);
}
__device__ __forceinline__ float u2f(unsigned u) {
    return __uint_as_float((u & 0x80000000u) ? (u & 0x7fffffffu) : ~u);
}
__device__ __forceinline__ float sigm(float z) { return 1.0f / (1.0f + expf(-z)); }

// Exact K-th largest via 4-pass radix-256 select over per-thread register
// values. All threads of the block must call. blockDim.x >= 256.
template<int M>
__device__ float kth_largest_radix256(const unsigned* uv, int K) {
    __shared__ unsigned s_hist[256];
    __shared__ int s_bin, s_k;
    unsigned prefix = 0;
    int k = K;
    #pragma unroll
    for (int shift = 24; shift >= 0; shift -= 8) {
        for (int b = threadIdx.x; b < 256; b += blockDim.x) s_hist[b] = 0;
        __syncthreads();
        unsigned hi = (shift == 24) ? 0u : (0xFFFFFFFFu << (shift + 8));
        #pragma unroll
        for (int j = 0; j < M; j++) {
            unsigned u = uv[j];
            if ((u & hi) == prefix) atomicAdd(&s_hist[(u >> shift) & 255], 1u);
        }
        __syncthreads();
        // parallel inclusive suffix sum: s_hist[b] = count(byte >= b)
        #pragma unroll
        for (int d = 1; d < 256; d <<= 1) {
            unsigned add = 0;
            if (threadIdx.x < 256)
                add = (threadIdx.x + d < 256) ? s_hist[threadIdx.x + d] : 0u;
            __syncthreads();
            if (threadIdx.x < 256) s_hist[threadIdx.x] += add;
            __syncthreads();
        }
        if (threadIdx.x < 256) {
            unsigned ge = s_hist[threadIdx.x];
            unsigned gt = (threadIdx.x == 255) ? 0u : s_hist[threadIdx.x + 1];
            if (ge >= (unsigned)k && gt < (unsigned)k) { s_bin = threadIdx.x; s_k = k - (int)gt; }
        }
        __syncthreads();
        prefix |= ((unsigned)s_bin) << shift;
        k = s_k;
        __syncthreads();
    }
    return u2f(prefix);
}

// K-th largest of x[0..n), global-read variant (256 threads).
__device__ float kth_global_256(const float* __restrict__ x, int n, int K) {
    __shared__ unsigned s_hist[256];
    __shared__ int s_bin, s_k;
    int tid = threadIdx.x;
    unsigned prefix = 0;
    int k = K;
    #pragma unroll
    for (int shift = 24; shift >= 0; shift -= 8) {
        s_hist[tid] = 0;
        __syncthreads();
        unsigned hi = (shift == 24) ? 0u : (0xFFFFFFFFu << (shift + 8));
        for (int i = tid; i < n; i += 256) {
            unsigned u = f2u(x[i]);
            if ((u & hi) == prefix) atomicAdd(&s_hist[(u >> shift) & 255], 1u);
        }
        __syncthreads();
        #pragma unroll
        for (int d = 1; d < 256; d <<= 1) {
            unsigned add = (tid + d < 256) ? s_hist[tid + d] : 0u;
            __syncthreads();
            s_hist[tid] += add;
            __syncthreads();
        }
        {
            unsigned ge = s_hist[tid];
            unsigned gt = (tid == 255) ? 0u : s_hist[tid + 1];
            if (ge >= (unsigned)k && gt < (unsigned)k) { s_bin = tid; s_k = k - (int)gt; }
        }
        __syncthreads();
        prefix |= ((unsigned)s_bin) << shift;
        k = s_k;
        __syncthreads();
    }
    return u2f(prefix);
}

// ---------------- L2 prefetch of W_ca3_ca1 head (fills stageA's DRAM bubble) ----------
// Reads the first 96 MB with ld.global.cg (cache at L2). update_W consumes the
// same lines first (sequential from idx 0), converting DRAM reads to L2 hits.
__global__ void prefetch_W_kernel(const float* __restrict__ W) {
    const float4* w4 = reinterpret_cast<const float4*>(W);
    const size_t n4 = (size_t)24 * 1024 * 1024 / 4;   // 96 MB = 6M float4
    float acc = 0.0f;
    for (size_t i = (size_t)blockIdx.x * blockDim.x + threadIdx.x; i < n4;
         i += (size_t)gridDim.x * blockDim.x) {
        float4 v = __ldcg(&w4[i]);
        acc += v.x + v.y + v.z + v.w;
    }
    if (acc == 1.2345e-30f) g_sink = acc;   // practically never true; keeps the loads
}

// ---------------- K1: h1 = W_ei_ca3 @ x, h3 = W_ei_ca1 @ x (one warp/row) ----------------
__global__ void matvec_dual_kernel(const float* __restrict__ Wa,
                                   const float* __restrict__ Wb,
                                   const float* __restrict__ x) {
    int warp = threadIdx.x >> 5, lane = threadIdx.x & 31;
    int row = blockIdx.x * 8 + warp;
    const float* W; float* out; int r;
    if (row < DIM_CA3) { W = Wa; out = g_h1; r = row; }
    else               { W = Wb; out = g_h3; r = row - DIM_CA3; }
    const float4* w4 = reinterpret_cast<const float4*>(W) + (size_t)r * (DIM_EI / 4);
    const float4* x4 = reinterpret_cast<const float4*>(x);
    float acc = 0.0f;
    #pragma unroll 8
    for (int i = lane; i < DIM_EI / 4; i += 32) {
        float4 w = __ldcs(&w4[i]);
        float4 v = __ldg(&x4[i]);
        acc += w.x * v.x + w.y * v.y + w.z * v.z + w.w * v.w;
    }
    #pragma unroll
    for (int o = 16; o; o >>= 1) acc += __shfl_down_sync(0xffffffffu, acc, o);
    if (lane == 0) out[r] = acc;
}

// ---------------- K2: block0 -> top-2(h1)+x_ca3+compaction; block1 -> top-100(h3)+IS ----
__global__ void stageA_kernel() {
    __shared__ int wsum[32];
    int lane = threadIdx.x & 31, wid = threadIdx.x >> 5;
    int base = threadIdx.x * 8;
    if (blockIdx.x == 0) {
        float xv[8]; unsigned uv[8];
        #pragma unroll
        for (int j = 0; j < 8; j++) { xv[j] = g_h1[base + j]; uv[j] = f2u(xv[j]); }
        float th = kth_largest_radix256<8>(uv, 2);
        float vals[8]; int keep[8]; int cnt = 0;
        #pragma unroll
        for (int j = 0; j < 8; j++) {
            int kp = (xv[j] >= th);
            float v = kp ? sigm(BETA * (xv[j] - th)) : 0.0f;
            g_xca3[base + j] = v;
            vals[j] = v; keep[j] = kp; cnt += kp;
        }
        // deterministic compaction: warp inclusive scan + block scan of 32 warps
        int incl = cnt;
        #pragma unroll
        for (int o = 1; o < 32; o <<= 1) {
            int n = __shfl_up_sync(0xffffffffu, incl, o);
            if (lane >= o) incl += n;
        }
        if (lane == 31) wsum[wid] = incl;
        __syncthreads();
        if (threadIdx.x == 0) {
            int s = 0;
            #pragma unroll
            for (int i = 0; i < 32; i++) { int c = wsum[i]; wsum[i] = s; s += c; }
            g_nnz_cnt = s;
            g_ctr = 0;   // reset "last block" counter for matvec_out
        }
        __syncthreads();
        int off = wsum[wid] + incl - cnt;
        #pragma unroll
        for (int j = 0; j < 8; j++) {
            if (keep[j]) { g_nnz_idx[off] = base + j; g_nnz_val[off] = vals[j]; ++off; }
        }
    } else {
        float xv[8]; unsigned uv[8];
        #pragma unroll
        for (int j = 0; j < 8; j++) { xv[j] = g_h3[base + j]; uv[j] = f2u(xv[j]); }
        float th = kth_largest_radix256<8>(uv, 100);
        #pragma unroll
        for (int j = 0; j < 8; j++)
            g_IS[base + j] = (xv[j] >= th) ? sigm(BETA * (xv[j] - th)) : 0.0f;
    }
}

// ---------------- K3: fused h2 gather (x_ca3 ~2 nnz) + top-100 + dense sigmoid ----------
__global__ void stageBC_kernel(const float* __restrict__ W3) {
    int cnt = g_nnz_cnt;
    int base = threadIdx.x * 8;
    float hv[8]; unsigned uv[8];
    #pragma unroll
    for (int r = 0; r < 8; r++) {
        size_t rowoff = (size_t)(base + r) * DIM_CA3;
        float acc = 0.0f;
        for (int k = 0; k < cnt; k++)
            acc += W3[rowoff + g_nnz_idx[k]] * g_nnz_val[k];
        hv[r] = acc; uv[r] = f2u(acc);
    }
    float th = kth_largest_radix256<8>(uv, 100);
    #pragma unroll
    for (int r = 0; r < 8; r++)
        g_xca1[base + r] = sigm(BETA * (hv[r] - th));   // flag=False: no hard mask
}

// ---------------- K4: W_new = (1-IS*a)*W + a*IS*x_ca3^T (row-broadcast FMA) ----------
__global__ void update_W_kernel(const float* __restrict__ W, float* __restrict__ out) {
    size_t idx = ((size_t)blockIdx.x * blockDim.x + threadIdx.x) * 4;
    int row = (int)(idx >> 13);          // / 8192
    int col = (int)(idx & (DIM_CA3 - 1));
    float s = g_IS[row];
    float a = 1.0f - s * ALPHA;
    float b = ALPHA * s;
    float4 w  = __ldcs(reinterpret_cast<const float4*>(W + idx));
    float4 xc = *reinterpret_cast<const float4*>(g_xca3 + col);
    float4 o;
    o.x = a * w.x + b * xc.x;
    o.y = a * w.y + b * xc.y;
    o.z = a * w.z + b * xc.z;
    o.w = a * w.w + b * xc.w;
    __stcs(reinterpret_cast<float4*>(out + idx), o);
}

// ---------------- K5: h4 = W_ca1_eo @ x_ca1; last block: top-50 + masked sigmoid ------
__global__ __launch_bounds__(256) void matvec_out_kernel(
        const float* __restrict__ W, float* __restrict__ out) {
    int warp = threadIdx.x >> 5, lane = threadIdx.x & 31;
    int tid = threadIdx.x;
    int row = blockIdx.x * 8 + warp;
    const float4* w4 = reinterpret_cast<const float4*>(W) + (size_t)row * (DIM_CA1 / 4);
    const float4* x4 = reinterpret_cast<const float4*>(g_xca1);
    float acc = 0.0f;
    #pragma unroll 8
    for (int i = lane; i < DIM_CA1 / 4; i += 32) {
        float4 w = __ldcs(&w4[i]);
        float4 v = __ldg(&x4[i]);
        acc += w.x * v.x + w.y * v.y + w.z * v.z + w.w * v.w;
    }
    #pragma unroll
    for (int o = 16; o; o >>= 1) acc += __shfl_down_sync(0xffffffffu, acc, o);
    if (lane == 0) {
        g_h4[row] = acc;
        __threadfence();
    }
    __syncthreads();
    __shared__ bool s_last;
    if (tid == 0) {
        unsigned t = atomicAdd(&g_ctr, 1u);
        s_last = (t == gridDim.x - 1);
    }
    __syncthreads();
    if (!s_last) return;
    __threadfence();
    // final select over h4 (4096 elems, 256 threads)
    float th = kth_global_256(g_h4, DIM_EO, 50);
    for (int i = tid; i < DIM_EO; i += 256) {
        float xx = g_h4[i];
        out[i] = (xx >= th) ? sigm(BETA * (xx - th)) : 0.0f;
    }
}

// ---------------- launch: R4 fork-join + L2 prefetch during stageA --------------------
extern "C" void kernel_launch(void* const* d_in, const int* in_sizes, int n_in,
                              void* d_out, int out_size) {
    const float* x_ei      = (const float*)d_in[0];
    const float* W_ei_ca3  = (const float*)d_in[1];
    const float* W_ei_ca1  = (const float*)d_in[2];
    const float* W_ca3_ca1 = (const float*)d_in[3];
    const float* W_ca1_eo  = (const float*)d_in[4];
    float* out = (float*)d_out;

    cudaStream_t s1;
    cudaStreamCreateWithFlags(&s1, cudaStreamNonBlocking);
    cudaEvent_t e_mv, e_fork, e_join;
    cudaEventCreateWithFlags(&e_mv,   cudaEventDisableTiming);
    cudaEventCreateWithFlags(&e_fork, cudaEventDisableTiming);
    cudaEventCreateWithFlags(&e_join, cudaEventDisableTiming);

    // s0: matvecs + selects
    matvec_dual_kernel<<<(DIM_CA3 + DIM_CA1) / 8, 256>>>(W_ei_ca3, W_ei_ca1, x_ei);
    cudaEventRecord(e_mv, 0);
    stageA_kernel<<<2, 1024>>>();
    cudaEventRecord(e_fork, 0);

    // s1: prefetch W head into L2 during stageA's DRAM bubble, then B-chain
    cudaStreamWaitEvent(s1, e_mv, 0);
    prefetch_W_kernel<<<1024, 256, 0, s1>>>(W_ca3_ca1);
    cudaStreamWaitEvent(s1, e_fork, 0);
    stageBC_kernel<<<1, 1024, 0, s1>>>(W_ca3_ca1);
    matvec_out_kernel<<<DIM_EO / 8, 256, 0, s1>>>(W_ca1_eo, out);
    cudaEventRecord(e_join, s1);

    // s0: big update (head reads now L2-hot)
    update_W_kernel<<<(unsigned)((size_t)DIM_CA1 * DIM_CA3 / 4 / 256), 256>>>(W_ca3_ca1, out + DIM_EO);
    cudaStreamWaitEvent(0, e_join, 0);

    cudaEventDestroy(e_mv);
    cudaEventDestroy(e_fork);
    cudaEventDestroy(e_join);
    cudaStreamDestroy(s1);
}

// round 12
// speedup vs baseline: 1.1172x; 1.1123x over previous
#include <cuda_runtime.h>
#include <math.h>

#define DIM_EI  4096
#define DIM_CA3 8192
#define DIM_CA1 8192
#define DIM_EO  4096

static constexpr float BETA  = 10.0f;
static constexpr float ALPHA = 0.01f;

// ---------------- device scratch ----------------
__device__ float g_h1[DIM_CA3];
__device__ float g_h3[DIM_CA1];
__device__ float g_h4[DIM_EO];
__device__ float g_xca3[DIM_CA3];
__device__ float g_IS[DIM_CA1];
__device__ float g_xca1[DIM_CA1];
__device__ int   g_nnz_idx[DIM_CA3];
__device__ float g_nnz_val[DIM_CA3];
__device__ int   g_nnz_cnt;
__device__ unsigned g_ctr;

// ---------------- helpers ----------------
__device__ __forceinline__ unsigned f2u(float f) {
    unsigned u = __float_as_uint(f);
    return (u & 0x80000000u) ? ~u : (u | 0x80000000u);
}
__device__ __forceinline__ float u2f(unsigned u) {
    return __uint_as_float((u & 0x80000000u) ? (u & 0x7fffffffu) : ~u);
}
__device__ __forceinline__ float sigm(float z) { return 1.0f / (1.0f + expf(-z)); }

// Warp-aggregated histogram add (conflict-free for hot bins).
__device__ __forceinline__ void hist_add(unsigned* s_hist, int bin, bool pred) {
    unsigned active = __ballot_sync(0xffffffffu, pred);
    if (pred) {
        unsigned mask = __match_any_sync(active, bin);
        int leader = __ffs(mask) - 1;
        if ((int)(threadIdx.x & 31) == leader)
            atomicAdd(&s_hist[bin], (unsigned)__popc(mask));
    }
}

// Warp 0 locates the bin holding the k-th largest in a 256-bin histogram.
__device__ __forceinline__ void find_bin_warp0(const unsigned* s_hist, int k,
                                               int* s_bin, int* s_k) {
    if (threadIdx.x < 32) {
        int lane = threadIdx.x;
        unsigned b[8]; unsigned tot = 0;
        #pragma unroll
        for (int j = 0; j < 8; j++) { b[j] = s_hist[lane * 8 + j]; tot += b[j]; }
        unsigned suf = tot;
        #pragma unroll
        for (int o = 1; o < 32; o <<= 1) {
            unsigned n = __shfl_down_sync(0xffffffffu, suf, o);
            if (lane + o < 32) suf += n;
        }
        unsigned above = suf - tot;
        unsigned ge[8]; unsigned run = above;
        #pragma unroll
        for (int j = 7; j >= 0; j--) { run += b[j]; ge[j] = run; }
        unsigned gt = above;
        #pragma unroll
        for (int j = 7; j >= 0; j--) {
            if (ge[j] >= (unsigned)k && gt < (unsigned)k) {
                *s_bin = lane * 8 + j;
                *s_k   = k - (int)gt;
            }
            gt = ge[j];
        }
    }
}

// Exact K-th largest via candidate compaction: pass 1 = top-byte histogram over
// all M*blockDim values; then only the ~candidates sharing the selected top
// byte go through 3 more radix passes (in smem). Full-pass fallback if the
// candidate set exceeds the buffer. blockDim.x >= 256, all threads call.
template<int M>
__device__ float kth_select(const unsigned* uv, int K) {
    __shared__ unsigned s_hist[256];
    __shared__ unsigned s_cand[2048];
    __shared__ int s_bin, s_k, s_cnt;
    // ---- pass 1 over all values (top byte) ----
    if (threadIdx.x < 256) s_hist[threadIdx.x] = 0;
    __syncthreads();
    #pragma unroll
    for (int j = 0; j < M; j++) hist_add(s_hist, uv[j] >> 24, true);
    __syncthreads();
    find_bin_warp0(s_hist, K, &s_bin, &s_k);
    __syncthreads();
    unsigned b0 = (unsigned)s_bin;
    int k = s_k;
    unsigned prefix = b0 << 24;
    // ---- compact candidates (order-independent; only the value matters) ----
    if (threadIdx.x == 0) s_cnt = 0;
    __syncthreads();
    #pragma unroll
    for (int j = 0; j < M; j++) {
        if ((uv[j] >> 24) == b0) {
            int pos = atomicAdd(&s_cnt, 1);
            if (pos < 2048) s_cand[pos] = uv[j];
        }
    }
    __syncthreads();
    int cnt = s_cnt;
    if (cnt <= 2048) {
        // ---- passes 2-4 over ~cnt candidates only ----
        #pragma unroll
        for (int shift = 16; shift >= 0; shift -= 8) {
            unsigned hi = 0xFFFFFFFFu << (shift + 8);
            if (threadIdx.x < 256) s_hist[threadIdx.x] = 0;
            __syncthreads();
            for (int i = threadIdx.x; i < cnt; i += blockDim.x) {
                unsigned u = s_cand[i];
                if ((u & hi) == prefix) atomicAdd(&s_hist[(u >> shift) & 255], 1u);
            }
            __syncthreads();
            find_bin_warp0(s_hist, k, &s_bin, &s_k);
            __syncthreads();
            prefix |= ((unsigned)s_bin) << shift;
            k = s_k;
            __syncthreads();
        }
        return u2f(prefix);
    }
    // ---- fallback: full passes (pathological tie flood) ----
    #pragma unroll
    for (int shift = 16; shift >= 0; shift -= 8) {
        unsigned hi = 0xFFFFFFFFu << (shift + 8);
        if (threadIdx.x < 256) s_hist[threadIdx.x] = 0;
        __syncthreads();
        #pragma unroll
        for (int j = 0; j < M; j++) {
            unsigned u = uv[j];
            hist_add(s_hist, (u >> shift) & 255, (u & hi) == prefix);
        }
        __syncthreads();
        find_bin_warp0(s_hist, k, &s_bin, &s_k);
        __syncthreads();
        prefix |= ((unsigned)s_bin) << shift;
        k = s_k;
        __syncthreads();
    }
    return u2f(prefix);
}

// ---------------- K1: h1 = W_ei_ca3 @ x, h3 = W_ei_ca1 @ x (one warp/row) ----------------
__global__ void matvec_dual_kernel(const float* __restrict__ Wa,
                                   const float* __restrict__ Wb,
                                   const float* __restrict__ x) {
    int warp = threadIdx.x >> 5, lane = threadIdx.x & 31;
    int row = blockIdx.x * 8 + warp;
    const float* W; float* out; int r;
    if (row < DIM_CA3) { W = Wa; out = g_h1; r = row; }
    else               { W = Wb; out = g_h3; r = row - DIM_CA3; }
    const float4* w4 = reinterpret_cast<const float4*>(W) + (size_t)r * (DIM_EI / 4);
    const float4* x4 = reinterpret_cast<const float4*>(x);
    float acc = 0.0f;
    #pragma unroll 8
    for (int i = lane; i < DIM_EI / 4; i += 32) {
        float4 w = __ldcs(&w4[i]);
        float4 v = __ldg(&x4[i]);
        acc += w.x * v.x + w.y * v.y + w.z * v.z + w.w * v.w;
    }
    #pragma unroll
    for (int o = 16; o; o >>= 1) acc += __shfl_down_sync(0xffffffffu, acc, o);
    if (lane == 0) out[r] = acc;
}

// ---------------- K2: block0 -> top-2(h1)+x_ca3+compaction; block1 -> top-100(h3)+IS ----
__global__ void stageA_kernel() {
    __shared__ int wsum[32];
    int lane = threadIdx.x & 31, wid = threadIdx.x >> 5;
    int base = threadIdx.x * 8;
    if (blockIdx.x == 0) {
        float xv[8]; unsigned uv[8];
        #pragma unroll
        for (int j = 0; j < 8; j++) { xv[j] = g_h1[base + j]; uv[j] = f2u(xv[j]); }
        float th = kth_select<8>(uv, 2);
        float vals[8]; int keep[8]; int cnt = 0;
        #pragma unroll
        for (int j = 0; j < 8; j++) {
            int kp = (xv[j] >= th);
            float v = kp ? sigm(BETA * (xv[j] - th)) : 0.0f;
            g_xca3[base + j] = v;
            vals[j] = v; keep[j] = kp; cnt += kp;
        }
        // deterministic compaction: warp inclusive scan + block scan of 32 warps
        int incl = cnt;
        #pragma unroll
        for (int o = 1; o < 32; o <<= 1) {
            int n = __shfl_up_sync(0xffffffffu, incl, o);
            if (lane >= o) incl += n;
        }
        if (lane == 31) wsum[wid] = incl;
        __syncthreads();
        if (threadIdx.x == 0) {
            int s = 0;
            #pragma unroll
            for (int i = 0; i < 32; i++) { int c = wsum[i]; wsum[i] = s; s += c; }
            g_nnz_cnt = s;
            g_ctr = 0;   // reset "last block" counter for matvec_out
        }
        __syncthreads();
        int off = wsum[wid] + incl - cnt;
        #pragma unroll
        for (int j = 0; j < 8; j++) {
            if (keep[j]) { g_nnz_idx[off] = base + j; g_nnz_val[off] = vals[j]; ++off; }
        }
    } else {
        float xv[8]; unsigned uv[8];
        #pragma unroll
        for (int j = 0; j < 8; j++) { xv[j] = g_h3[base + j]; uv[j] = f2u(xv[j]); }
        float th = kth_select<8>(uv, 100);
        #pragma unroll
        for (int j = 0; j < 8; j++)
            g_IS[base + j] = (xv[j] >= th) ? sigm(BETA * (xv[j] - th)) : 0.0f;
    }
}

// ---------------- K3: fused h2 gather (x_ca3 ~2 nnz) + top-100 + dense sigmoid ----------
__global__ void stageBC_kernel(const float* __restrict__ W3) {
    int cnt = g_nnz_cnt;
    int base = threadIdx.x * 8;
    float hv[8]; unsigned uv[8];
    #pragma unroll
    for (int r = 0; r < 8; r++) {
        size_t rowoff = (size_t)(base + r) * DIM_CA3;
        float acc = 0.0f;
        for (int k = 0; k < cnt; k++)
            acc += W3[rowoff + g_nnz_idx[k]] * g_nnz_val[k];
        hv[r] = acc; uv[r] = f2u(acc);
    }
    float th = kth_select<8>(uv, 100);
    #pragma unroll
    for (int r = 0; r < 8; r++)
        g_xca1[base + r] = sigm(BETA * (hv[r] - th));   // flag=False: no hard mask
}

// ---------------- K4: W_new = (1-IS*a)*W + a*IS*x_ca3^T (32B per thread) --------------
__global__ void update_W_kernel(const float* __restrict__ W, float* __restrict__ out) {
    size_t idx = ((size_t)blockIdx.x * blockDim.x + threadIdx.x) * 8;
    int row = (int)(idx >> 13);          // / 8192 (constant within a block)
    int col = (int)(idx & (DIM_CA3 - 1));
    float s = g_IS[row];
    float a = 1.0f - s * ALPHA;
    float b = ALPHA * s;
    float4 w0 = __ldcs(reinterpret_cast<const float4*>(W + idx));
    float4 w1 = __ldcs(reinterpret_cast<const float4*>(W + idx + 4));
    float4 x0 = *reinterpret_cast<const float4*>(g_xca3 + col);
    float4 x1 = *reinterpret_cast<const float4*>(g_xca3 + col + 4);
    float4 o0, o1;
    o0.x = a * w0.x + b * x0.x;  o0.y = a * w0.y + b * x0.y;
    o0.z = a * w0.z + b * x0.z;  o0.w = a * w0.w + b * x0.w;
    o1.x = a * w1.x + b * x1.x;  o1.y = a * w1.y + b * x1.y;
    o1.z = a * w1.z + b * x1.z;  o1.w = a * w1.w + b * x1.w;
    __stcs(reinterpret_cast<float4*>(out + idx), o0);
    __stcs(reinterpret_cast<float4*>(out + idx + 4), o1);
}

// ---------------- K5: h4 = W_ca1_eo @ x_ca1; last block: top-50 + masked sigmoid ------
__global__ __launch_bounds__(256) void matvec_out_kernel(
        const float* __restrict__ W, float* __restrict__ out) {
    int warp = threadIdx.x >> 5, lane = threadIdx.x & 31;
    int tid = threadIdx.x;
    int row = blockIdx.x * 8 + warp;
    const float4* w4 = reinterpret_cast<const float4*>(W) + (size_t)row * (DIM_CA1 / 4);
    const float4* x4 = reinterpret_cast<const float4*>(g_xca1);
    float acc = 0.0f;
    #pragma unroll 8
    for (int i = lane; i < DIM_CA1 / 4; i += 32) {
        float4 w = __ldcs(&w4[i]);
        float4 v = __ldg(&x4[i]);
        acc += w.x * v.x + w.y * v.y + w.z * v.z + w.w * v.w;
    }
    #pragma unroll
    for (int o = 16; o; o >>= 1) acc += __shfl_down_sync(0xffffffffu, acc, o);
    if (lane == 0) {
        g_h4[row] = acc;
        __threadfence();
    }
    __syncthreads();
    __shared__ bool s_last;
    if (tid == 0) {
        unsigned t = atomicAdd(&g_ctr, 1u);
        s_last = (t == gridDim.x - 1);
    }
    __syncthreads();
    if (!s_last) return;
    __threadfence();
    // final select over h4 (4096 elems, 256 threads, 16 regs each)
    unsigned uv[16];
    #pragma unroll
    for (int j = 0; j < 16; j++) uv[j] = f2u(g_h4[tid * 16 + j]);
    float th = kth_select<16>(uv, 50);
    for (int i = tid; i < DIM_EO; i += 256) {
        float xx = g_h4[i];
        out[i] = (xx >= th) ? sigm(BETA * (xx - th)) : 0.0f;
    }
}

// ---------------- launch: R4 fork-join structure (the 176.9us winner) -----------------
extern "C" void kernel_launch(void* const* d_in, const int* in_sizes, int n_in,
                              void* d_out, int out_size) {
    const float* x_ei      = (const float*)d_in[0];
    const float* W_ei_ca3  = (const float*)d_in[1];
    const float* W_ei_ca1  = (const float*)d_in[2];
    const float* W_ca3_ca1 = (const float*)d_in[3];
    const float* W_ca1_eo  = (const float*)d_in[4];
    float* out = (float*)d_out;

    cudaStream_t s1;
    cudaStreamCreateWithFlags(&s1, cudaStreamNonBlocking);
    cudaEvent_t e_fork, e_join;
    cudaEventCreateWithFlags(&e_fork, cudaEventDisableTiming);
    cudaEventCreateWithFlags(&e_join, cudaEventDisableTiming);

    matvec_dual_kernel<<<(DIM_CA3 + DIM_CA1) / 8, 256>>>(W_ei_ca3, W_ei_ca1, x_ei);
    stageA_kernel<<<2, 1024>>>();

    // fork: B-chain on s1, concurrent with update_W on stream0
    cudaEventRecord(e_fork, 0);
    cudaStreamWaitEvent(s1, e_fork, 0);

    stageBC_kernel<<<1, 1024, 0, s1>>>(W_ca3_ca1);
    matvec_out_kernel<<<DIM_EO / 8, 256, 0, s1>>>(W_ca1_eo, out);

    update_W_kernel<<<(unsigned)((size_t)DIM_CA1 * DIM_CA3 / 8 / 256), 256>>>(W_ca3_ca1, out + DIM_EO);

    // join
    cudaEventRecord(e_join, s1);
    cudaStreamWaitEvent(0, e_join, 0);

    cudaEventDestroy(e_fork);
    cudaEventDestroy(e_join);
    cudaStreamDestroy(s1);
}

// round 13
// speedup vs baseline: 1.1737x; 1.0505x over previous
#include <cuda_runtime.h>
#include <math.h>

#define DIM_EI  4096
#define DIM_CA3 8192
#define DIM_CA1 8192
#define DIM_EO  4096

static constexpr float BETA  = 10.0f;
static constexpr float ALPHA = 0.01f;

// ---------------- device scratch ----------------
__device__ float g_h1[DIM_CA3];
__device__ float g_h3[DIM_CA1];
__device__ float g_h4[DIM_EO];
__device__ float g_xca3[DIM_CA3];
__device__ float g_IS[DIM_CA1];
__device__ float g_xca1[DIM_CA1];
__device__ int   g_nnz_idx[DIM_CA3];
__device__ float g_nnz_val[DIM_CA3];
__device__ int   g_nnz_cnt;
__device__ unsigned g_ctr;

// ---------------- helpers ----------------
__device__ __forceinline__ unsigned f2u(float f) {
    unsigned u = __float_as_uint(f);
    return (u & 0x80000000u) ? ~u : (u | 0x80000000u);
}
__device__ __forceinline__ float u2f(unsigned u) {
    return __uint_as_float((u & 0x80000000u) ? (u & 0x7fffffffu) : ~u);
}
__device__ __forceinline__ float sigm(float z) { return 1.0f / (1.0f + expf(-z)); }
__device__ __forceinline__ float dot4(float4 a, float4 b) {
    return a.x * b.x + a.y * b.y + a.z * b.z + a.w * b.w;
}

// Block reduction (256 threads) -> result valid on thread 0.
__device__ __forceinline__ float block_reduce_256(float v) {
    __shared__ float sp[8];
    int lane = threadIdx.x & 31, wid = threadIdx.x >> 5;
    #pragma unroll
    for (int o = 16; o; o >>= 1) v += __shfl_down_sync(0xffffffffu, v, o);
    if (lane == 0) sp[wid] = v;
    __syncthreads();
    if (threadIdx.x < 32) {
        v = (lane < 8) ? sp[lane] : 0.0f;
        #pragma unroll
        for (int o = 4; o; o >>= 1) v += __shfl_down_sync(0xffffffffu, v, o);
    }
    return v;
}

// Warp-aggregated histogram add (conflict-free for hot bins).
__device__ __forceinline__ void hist_add(unsigned* s_hist, int bin, bool pred) {
    unsigned active = __ballot_sync(0xffffffffu, pred);
    if (pred) {
        unsigned mask = __match_any_sync(active, bin);
        int leader = __ffs(mask) - 1;
        if ((int)(threadIdx.x & 31) == leader)
            atomicAdd(&s_hist[bin], (unsigned)__popc(mask));
    }
}

// Warp 0 locates the bin holding the k-th largest in a 256-bin histogram.
__device__ __forceinline__ void find_bin_warp0(const unsigned* s_hist, int k,
                                               int* s_bin, int* s_k) {
    if (threadIdx.x < 32) {
        int lane = threadIdx.x;
        unsigned b[8]; unsigned tot = 0;
        #pragma unroll
        for (int j = 0; j < 8; j++) { b[j] = s_hist[lane * 8 + j]; tot += b[j]; }
        unsigned suf = tot;
        #pragma unroll
        for (int o = 1; o < 32; o <<= 1) {
            unsigned n = __shfl_down_sync(0xffffffffu, suf, o);
            if (lane + o < 32) suf += n;
        }
        unsigned above = suf - tot;
        unsigned ge[8]; unsigned run = above;
        #pragma unroll
        for (int j = 7; j >= 0; j--) { run += b[j]; ge[j] = run; }
        unsigned gt = above;
        #pragma unroll
        for (int j = 7; j >= 0; j--) {
            if (ge[j] >= (unsigned)k && gt < (unsigned)k) {
                *s_bin = lane * 8 + j;
                *s_k   = k - (int)gt;
            }
            gt = ge[j];
        }
    }
}

// Exact K-th largest via candidate compaction (pass 1 full, passes 2-4 over
// the ~candidates sharing the selected top byte). Fallback: full passes.
template<int M>
__device__ float kth_select(const unsigned* uv, int K) {
    __shared__ unsigned s_hist[256];
    __shared__ unsigned s_cand[2048];
    __shared__ int s_bin, s_k, s_cnt;
    if (threadIdx.x < 256) s_hist[threadIdx.x] = 0;
    __syncthreads();
    #pragma unroll
    for (int j = 0; j < M; j++) hist_add(s_hist, uv[j] >> 24, true);
    __syncthreads();
    find_bin_warp0(s_hist, K, &s_bin, &s_k);
    __syncthreads();
    unsigned b0 = (unsigned)s_bin;
    int k = s_k;
    unsigned prefix = b0 << 24;
    if (threadIdx.x == 0) s_cnt = 0;
    __syncthreads();
    #pragma unroll
    for (int j = 0; j < M; j++) {
        if ((uv[j] >> 24) == b0) {
            int pos = atomicAdd(&s_cnt, 1);
            if (pos < 2048) s_cand[pos] = uv[j];
        }
    }
    __syncthreads();
    int cnt = s_cnt;
    if (cnt <= 2048) {
        #pragma unroll
        for (int shift = 16; shift >= 0; shift -= 8) {
            unsigned hi = 0xFFFFFFFFu << (shift + 8);
            if (threadIdx.x < 256) s_hist[threadIdx.x] = 0;
            __syncthreads();
            for (int i = threadIdx.x; i < cnt; i += blockDim.x) {
                unsigned u = s_cand[i];
                if ((u & hi) == prefix) atomicAdd(&s_hist[(u >> shift) & 255], 1u);
            }
            __syncthreads();
            find_bin_warp0(s_hist, k, &s_bin, &s_k);
            __syncthreads();
            prefix |= ((unsigned)s_bin) << shift;
            k = s_k;
            __syncthreads();
        }
        return u2f(prefix);
    }
    #pragma unroll
    for (int shift = 16; shift >= 0; shift -= 8) {
        unsigned hi = 0xFFFFFFFFu << (shift + 8);
        if (threadIdx.x < 256) s_hist[threadIdx.x] = 0;
        __syncthreads();
        #pragma unroll
        for (int j = 0; j < M; j++) {
            unsigned u = uv[j];
            hist_add(s_hist, (u >> shift) & 255, (u & hi) == prefix);
        }
        __syncthreads();
        find_bin_warp0(s_hist, k, &s_bin, &s_k);
        __syncthreads();
        prefix |= ((unsigned)s_bin) << shift;
        k = s_k;
        __syncthreads();
    }
    return u2f(prefix);
}

// ---------------- K1: dual matvec, BLOCK-per-row (grid 16384) -------------------------
// Front-batched 4 independent float4 loads/thread -> high MLP_p1, update_W-like grid.
__global__ __launch_bounds__(256) void matvec_dual_kernel(
        const float* __restrict__ Wa, const float* __restrict__ Wb,
        const float* __restrict__ x) {
    int r = blockIdx.x;
    const float* W; float* out;
    if (r < DIM_CA3) { W = Wa; out = g_h1; }
    else             { W = Wb; out = g_h3; r -= DIM_CA3; }
    const float4* w4 = reinterpret_cast<const float4*>(W) + (size_t)r * (DIM_EI / 4);
    const float4* x4 = reinterpret_cast<const float4*>(x);
    int t = threadIdx.x;
    float4 a0 = __ldcs(&w4[t]);
    float4 a1 = __ldcs(&w4[t + 256]);
    float4 a2 = __ldcs(&w4[t + 512]);
    float4 a3 = __ldcs(&w4[t + 768]);
    float4 b0 = __ldg(&x4[t]);
    float4 b1 = __ldg(&x4[t + 256]);
    float4 b2 = __ldg(&x4[t + 512]);
    float4 b3 = __ldg(&x4[t + 768]);
    float acc = dot4(a0, b0) + dot4(a1, b1) + dot4(a2, b2) + dot4(a3, b3);
    float sum = block_reduce_256(acc);
    if (threadIdx.x == 0) out[r] = sum;
}

// ---------------- K2: block0 -> top-2(h1)+x_ca3+compaction; block1 -> top-100(h3)+IS ----
__global__ void stageA_kernel() {
    __shared__ int wsum[32];
    int lane = threadIdx.x & 31, wid = threadIdx.x >> 5;
    int base = threadIdx.x * 8;
    if (blockIdx.x == 0) {
        float xv[8]; unsigned uv[8];
        #pragma unroll
        for (int j = 0; j < 8; j++) { xv[j] = g_h1[base + j]; uv[j] = f2u(xv[j]); }
        float th = kth_select<8>(uv, 2);
        float vals[8]; int keep[8]; int cnt = 0;
        #pragma unroll
        for (int j = 0; j < 8; j++) {
            int kp = (xv[j] >= th);
            float v = kp ? sigm(BETA * (xv[j] - th)) : 0.0f;
            g_xca3[base + j] = v;
            vals[j] = v; keep[j] = kp; cnt += kp;
        }
        int incl = cnt;
        #pragma unroll
        for (int o = 1; o < 32; o <<= 1) {
            int n = __shfl_up_sync(0xffffffffu, incl, o);
            if (lane >= o) incl += n;
        }
        if (lane == 31) wsum[wid] = incl;
        __syncthreads();
        if (threadIdx.x == 0) {
            int s = 0;
            #pragma unroll
            for (int i = 0; i < 32; i++) { int c = wsum[i]; wsum[i] = s; s += c; }
            g_nnz_cnt = s;
            g_ctr = 0;
        }
        __syncthreads();
        int off = wsum[wid] + incl - cnt;
        #pragma unroll
        for (int j = 0; j < 8; j++) {
            if (keep[j]) { g_nnz_idx[off] = base + j; g_nnz_val[off] = vals[j]; ++off; }
        }
    } else {
        float xv[8]; unsigned uv[8];
        #pragma unroll
        for (int j = 0; j < 8; j++) { xv[j] = g_h3[base + j]; uv[j] = f2u(xv[j]); }
        float th = kth_select<8>(uv, 100);
        #pragma unroll
        for (int j = 0; j < 8; j++)
            g_IS[base + j] = (xv[j] >= th) ? sigm(BETA * (xv[j] - th)) : 0.0f;
    }
}

// ---------------- K3: fused h2 gather (x_ca3 ~2 nnz) + top-100 + dense sigmoid ----------
__global__ void stageBC_kernel(const float* __restrict__ W3) {
    int cnt = g_nnz_cnt;
    int base = threadIdx.x * 8;
    float hv[8]; unsigned uv[8];
    #pragma unroll
    for (int r = 0; r < 8; r++) {
        size_t rowoff = (size_t)(base + r) * DIM_CA3;
        float acc = 0.0f;
        for (int k = 0; k < cnt; k++)
            acc += W3[rowoff + g_nnz_idx[k]] * g_nnz_val[k];
        hv[r] = acc; uv[r] = f2u(acc);
    }
    float th = kth_select<8>(uv, 100);
    #pragma unroll
    for (int r = 0; r < 8; r++)
        g_xca1[base + r] = sigm(BETA * (hv[r] - th));   // flag=False: no hard mask
}

// ---------------- K4: W_new = (1-IS*a)*W + a*IS*x_ca3^T (32B per thread) --------------
__global__ void update_W_kernel(const float* __restrict__ W, float* __restrict__ out) {
    size_t idx = ((size_t)blockIdx.x * blockDim.x + threadIdx.x) * 8;
    int row = (int)(idx >> 13);
    int col = (int)(idx & (DIM_CA3 - 1));
    float s = g_IS[row];
    float a = 1.0f - s * ALPHA;
    float b = ALPHA * s;
    float4 w0 = __ldcs(reinterpret_cast<const float4*>(W + idx));
    float4 w1 = __ldcs(reinterpret_cast<const float4*>(W + idx + 4));
    float4 x0 = *reinterpret_cast<const float4*>(g_xca3 + col);
    float4 x1 = *reinterpret_cast<const float4*>(g_xca3 + col + 4);
    float4 o0, o1;
    o0.x = a * w0.x + b * x0.x;  o0.y = a * w0.y + b * x0.y;
    o0.z = a * w0.z + b * x0.z;  o0.w = a * w0.w + b * x0.w;
    o1.x = a * w1.x + b * x1.x;  o1.y = a * w1.y + b * x1.y;
    o1.z = a * w1.z + b * x1.z;  o1.w = a * w1.w + b * x1.w;
    __stcs(reinterpret_cast<float4*>(out + idx), o0);
    __stcs(reinterpret_cast<float4*>(out + idx + 4), o1);
}

// ---------------- K5: matvec_out BLOCK-per-row (grid 4096) + fused top-50 tail --------
__global__ __launch_bounds__(256) void matvec_out_kernel(
        const float* __restrict__ W, float* __restrict__ out) {
    int r = blockIdx.x;
    int tid = threadIdx.x;
    const float4* w4 = reinterpret_cast<const float4*>(W) + (size_t)r * (DIM_CA1 / 4);
    const float4* x4 = reinterpret_cast<const float4*>(g_xca1);
    float acc = 0.0f;
    // 8 front-batched independent float4 loads (row = 8192 floats = 2048 float4)
    float4 a0 = __ldcs(&w4[tid]);
    float4 a1 = __ldcs(&w4[tid + 256]);
    float4 a2 = __ldcs(&w4[tid + 512]);
    float4 a3 = __ldcs(&w4[tid + 768]);
    float4 a4 = __ldcs(&w4[tid + 1024]);
    float4 a5 = __ldcs(&w4[tid + 1280]);
    float4 a6 = __ldcs(&w4[tid + 1536]);
    float4 a7 = __ldcs(&w4[tid + 1792]);
    acc += dot4(a0, __ldg(&x4[tid]));
    acc += dot4(a1, __ldg(&x4[tid + 256]));
    acc += dot4(a2, __ldg(&x4[tid + 512]));
    acc += dot4(a3, __ldg(&x4[tid + 768]));
    acc += dot4(a4, __ldg(&x4[tid + 1024]));
    acc += dot4(a5, __ldg(&x4[tid + 1280]));
    acc += dot4(a6, __ldg(&x4[tid + 1536]));
    acc += dot4(a7, __ldg(&x4[tid + 1792]));
    float sum = block_reduce_256(acc);
    if (tid == 0) {
        g_h4[r] = sum;
        __threadfence();
    }
    __syncthreads();
    __shared__ bool s_last;
    if (tid == 0) {
        unsigned t = atomicAdd(&g_ctr, 1u);
        s_last = (t == gridDim.x - 1);
    }
    __syncthreads();
    if (!s_last) return;
    __threadfence();
    // final select over h4 (4096 elems, 256 threads, 16 regs each)
    unsigned uv[16];
    #pragma unroll
    for (int j = 0; j < 16; j++) uv[j] = f2u(g_h4[tid * 16 + j]);
    float th = kth_select<16>(uv, 50);
    for (int i = tid; i < DIM_EO; i += 256) {
        float xx = g_h4[i];
        out[i] = (xx >= th) ? sigm(BETA * (xx - th)) : 0.0f;
    }
}

// ---------------- launch: R4 fork-join structure ----------------
extern "C" void kernel_launch(void* const* d_in, const int* in_sizes, int n_in,
                              void* d_out, int out_size) {
    const float* x_ei      = (const float*)d_in[0];
    const float* W_ei_ca3  = (const float*)d_in[1];
    const float* W_ei_ca1  = (const float*)d_in[2];
    const float* W_ca3_ca1 = (const float*)d_in[3];
    const float* W_ca1_eo  = (const float*)d_in[4];
    float* out = (float*)d_out;

    cudaStream_t s1;
    cudaStreamCreateWithFlags(&s1, cudaStreamNonBlocking);
    cudaEvent_t e_fork, e_join;
    cudaEventCreateWithFlags(&e_fork, cudaEventDisableTiming);
    cudaEventCreateWithFlags(&e_join, cudaEventDisableTiming);

    matvec_dual_kernel<<<DIM_CA3 + DIM_CA1, 256>>>(W_ei_ca3, W_ei_ca1, x_ei);
    stageA_kernel<<<2, 1024>>>();

    // fork: B-chain on s1, concurrent with update_W on stream0
    cudaEventRecord(e_fork, 0);
    cudaStreamWaitEvent(s1, e_fork, 0);

    stageBC_kernel<<<1, 1024, 0, s1>>>(W_ca3_ca1);
    matvec_out_kernel<<<DIM_EO, 256, 0, s1>>>(W_ca1_eo, out);

    update_W_kernel<<<(unsigned)((size_t)DIM_CA1 * DIM_CA3 / 8 / 256), 256>>>(W_ca3_ca1, out + DIM_EO);

    // join
    cudaEventRecord(e_join, s1);
    cudaStreamWaitEvent(0, e_join, 0);

    cudaEventDestroy(e_fork);
    cudaEventDestroy(e_join);
    cudaStreamDestroy(s1);
}